// round 6
// baseline (speedup 1.0000x reference)
#include <cuda_runtime.h>
#include <cstdint>

#define N_NODES 100000
#define N_EDGES 1600000
#define C_HID   128
#define E_DIM   32
#define C_OUT   64
#define N_LAYERS 4

typedef unsigned long long ull;

// ---------------- scratch (static device globals; no allocation) ----------------
__device__ float g_x  [(size_t)N_NODES * C_HID];
__device__ float g_agg[(size_t)N_NODES * C_HID];
__device__ int   g_idx64_flag;

// ---------------- packed fp32 helpers --------------------------------------------
__device__ __forceinline__ ull pack2(float x, float y) {
    ull r; asm("mov.b64 %0, {%1, %2};" : "=l"(r) : "f"(x), "f"(y)); return r;
}
__device__ __forceinline__ float2 unpack2(ull v) {
    float2 r; asm("mov.b64 {%0, %1}, %2;" : "=f"(r.x), "=f"(r.y) : "l"(v)); return r;
}
__device__ __forceinline__ void fma2(ull& acc, ull a, ull b) {
    asm("fma.rn.f32x2 %0, %1, %2, %0;" : "+l"(acc) : "l"(a), "l"(b));
}
__device__ __forceinline__ void red4(float* p, float4 v) {
    asm volatile("red.global.add.v4.f32 [%0], {%1, %2, %3, %4};"
                 :: "l"(p), "f"(v.x), "f"(v.y), "f"(v.z), "f"(v.w) : "memory");
}
__device__ __forceinline__ void cp16(unsigned int s, const void* g) {
    asm volatile("cp.async.ca.shared.global [%0], [%1], 16;" :: "r"(s), "l"(g));
}
__device__ __forceinline__ void cp_commit() {
    asm volatile("cp.async.commit_group;");
}

// copy one 8192-float (32KB) weight slab: 256 threads x 8 x 16B
__device__ __forceinline__ void cp_slab(float* dst, const float* src, int tid) {
    unsigned int s = (unsigned int)__cvta_generic_to_shared(dst) + tid * 16;
    const char* g = (const char*)src + tid * 16;
    #pragma unroll
    for (int i = 0; i < 8; i++) cp16(s + i * 4096, g + i * 4096);
    cp_commit();
}

// ---------------- dtype probe: edge_index int64 vs int32 -------------------------
__global__ void probe_kernel(const int* __restrict__ ei) {
    if (threadIdx.x == 0 && blockIdx.x == 0) {
        int all0 = 1;
        for (int i = 1; i < 64; i += 2) all0 &= (ei[i] == 0);
        g_idx64_flag = all0;
    }
}

// ---------------- edge kernel v3: register-resident weights ----------------------
// Per warp-iter: 8 edges. k-loop issues NO shared/global loads: weights live in
// 64 regs/lane (lane owns channels 4l..4l+3 for all 32 k).
__global__ void __launch_bounds__(256, 2) edge_kernel(
    const float* __restrict__ ea, const void* __restrict__ ei_raw,
    const float* __restrict__ x, const float* __restrict__ We,
    const float* __restrict__ be, float* __restrict__ agg, int layer)
{
    const int lane   = threadIdx.x & 31;
    const int warp   = (blockIdx.x * blockDim.x + threadIdx.x) >> 5;
    const int nwarps = (gridDim.x * blockDim.x) >> 5;

    const int use64 = g_idx64_flag;
    const long long* ei64 = (const long long*)ei_raw;
    const int*       ei32 = (const int*)ei_raw;
    const float4*    x4   = (const float4*)x;

    // weights -> registers: w[k] = {We[k][4l],We[k][4l+1]},{We[k][4l+2],We[k][4l+3]}
    ulonglong2 w[E_DIM];
    const ulonglong2* Wg = (const ulonglong2*)(We + (size_t)layer * E_DIM * C_HID);
    #pragma unroll
    for (int k = 0; k < E_DIM; k++) w[k] = Wg[k * 32 + lane];

    const float4 bev = ((const float4*)(be + layer * C_HID))[lane];
    const ull be01 = pack2(bev.x, bev.y);
    const ull be23 = pack2(bev.z, bev.w);

    for (int p = warp; p < N_EDGES / 8; p += nwarps) {
        const int e0 = p * 8;

        float a[8];
        #pragma unroll
        for (int j = 0; j < 8; j++) a[j] = ea[(e0 + j) * E_DIM + lane];

        int sv = 0;
        if (lane < 16) {
            if (use64) {
                const long long* bp = (lane < 8) ? (ei64 + e0 + lane)
                                                 : (ei64 + N_EDGES + e0 + lane - 8);
                sv = (int)(*bp);
            } else {
                const int* bp = (lane < 8) ? (ei32 + e0 + lane)
                                           : (ei32 + N_EDGES + e0 + lane - 8);
                sv = *bp;
            }
        }

        ull accA[8], accB[8];
        #pragma unroll
        for (int j = 0; j < 8; j++) { accA[j] = be01; accB[j] = be23; }

        #pragma unroll
        for (int k = 0; k < E_DIM; k++) {
            #pragma unroll
            for (int j = 0; j < 8; j++) {
                const float ak = __shfl_sync(0xffffffffu, a[j], k);
                const ull av = pack2(ak, ak);
                fma2(accA[j], av, w[k].x);
                fma2(accB[j], av, w[k].y);
            }
        }

        #pragma unroll
        for (int j = 0; j < 8; j++) {
            const int s = __shfl_sync(0xffffffffu, sv, j);
            const int d = __shfl_sync(0xffffffffu, sv, 8 + j);
            const float4 xv = x4[(size_t)s * 32 + lane];
            const float2 pA = unpack2(accA[j]);
            const float2 pB = unpack2(accB[j]);
            float4 m;
            m.x = fmaxf(pA.x + xv.x, 0.f);
            m.y = fmaxf(pA.y + xv.y, 0.f);
            m.z = fmaxf(pB.x + xv.z, 0.f);
            m.w = fmaxf(pB.y + xv.w, 0.f);
            red4(agg + (size_t)d * C_HID + lane * 4, m);
        }
    }
}

// ---------------- node kernel v2: 64-node tiles, 2 cols/thread, cp.async db ------
#define NP 68
#define SM_H0T 0                        // 128*68 = 8704 floats (h2s aliases: 64*132)
#define SM_YT  8704                     // 256*68 = 17408 floats
#define SM_WSL (8704 + 17408)           // 2 x 8192 floats (double buffer)
#define NODE_SMEM ((8704 + 17408 + 16384) * 4)

__global__ void __launch_bounds__(256) node_kernel(
    float* __restrict__ x, const float* __restrict__ agg,
    const float* __restrict__ W1, const float* __restrict__ b1,
    const float* __restrict__ W2, const float* __restrict__ b2,
    const float* __restrict__ lnw, const float* __restrict__ lnb, int layer)
{
    extern __shared__ float sm[];
    float* h0T = sm + SM_H0T;
    float* h2s = sm + SM_H0T;          // alias (h0T dead after Phase B)
    float* yT  = sm + SM_YT;
    float* Wsl = sm + SM_WSL;

    const int tid = threadIdx.x;
    const int n0  = blockIdx.x * 64;

    const float* W1g = W1 + (size_t)layer * 128 * 256;
    const float* W2g = W2 + (size_t)layer * 256 * 128;

    cp_slab(Wsl, W1g, tid);            // prefetch W1 slab 0 under Phase A

    // ---- Phase A: h0T[k][n'] = x[n][k] + agg[n][k], n' = n ^ ((k>>2 & 7)<<2) ----
    {
        const float4* x4 = (const float4*)x;
        const float4* a4 = (const float4*)agg;
        #pragma unroll
        for (int it = 0; it < 8; it++) {
            const int idx  = tid + it * 256;      // 0..2047
            const int node = idx >> 5, kq = idx & 31;
            const int gn   = n0 + node;
            float4 xv = make_float4(0.f, 0.f, 0.f, 0.f), av = xv;
            if (gn < N_NODES) {
                xv = x4[(size_t)gn * 32 + kq];
                av = a4[(size_t)gn * 32 + kq];
            }
            const int nn = node ^ ((kq & 7) << 2);
            h0T[(4 * kq + 0) * NP + nn] = xv.x + av.x;
            h0T[(4 * kq + 1) * NP + nn] = xv.y + av.y;
            h0T[(4 * kq + 2) * NP + nn] = xv.z + av.z;
            h0T[(4 * kq + 3) * NP + nn] = xv.w + av.w;
        }
    }
    __syncthreads();

    // ---- Phase B: y = relu(h0 @ W1 + b1). thread = (col-pair cp, node-group g) ----
    const int cp = tid & 127, g = tid >> 7;        // cols {2cp,2cp+1}, nodes 32g..+31
    {
        ull acc[2][16];
        const float2 bb = *(const float2*)(b1 + layer * 256 + 2 * cp);
        #pragma unroll
        for (int q = 0; q < 16; q++) { acc[0][q] = pack2(bb.x, bb.x);
                                       acc[1][q] = pack2(bb.y, bb.y); }
        for (int s = 0; s < 4; s++) {
            float* buf = Wsl + (s & 1) * 8192;
            if (s < 3) cp_slab(Wsl + ((s + 1) & 1) * 8192, W1g + (s + 1) * 8192, tid);
            if (s < 3) asm volatile("cp.async.wait_group 1;");
            else       asm volatile("cp.async.wait_group 0;");
            __syncthreads();
            #pragma unroll 4
            for (int kk = 0; kk < 32; kk++) {
                const int k  = s * 32 + kk;
                const int sw = ((k >> 2) & 7) << 2;
                const float* hrow = h0T + k * NP + 32 * g;
                const float2 wv = *(const float2*)(buf + kk * 256 + 2 * cp);
                const ull w0 = pack2(wv.x, wv.x), w1 = pack2(wv.y, wv.y);
                #pragma unroll
                for (int c = 0; c < 8; c++) {
                    const ulonglong2 hv = *(const ulonglong2*)(hrow + ((4 * c) ^ sw));
                    fma2(acc[0][2 * c + 0], hv.x, w0);
                    fma2(acc[0][2 * c + 1], hv.y, w0);
                    fma2(acc[1][2 * c + 0], hv.x, w1);
                    fma2(acc[1][2 * c + 1], hv.y, w1);
                }
            }
            __syncthreads();
        }
        cp_slab(Wsl, W2g, tid);                    // prefetch W2 slab 0
        #pragma unroll
        for (int c = 0; c < 2; c++) {
            float* yrow = yT + (2 * cp + c) * NP + 32 * g;
            #pragma unroll
            for (int p = 0; p < 8; p++) {
                const float2 u = unpack2(acc[c][2 * p + 0]);
                const float2 v = unpack2(acc[c][2 * p + 1]);
                float4 o;
                o.x = fmaxf(u.x, 0.f); o.y = fmaxf(u.y, 0.f);
                o.z = fmaxf(v.x, 0.f); o.w = fmaxf(v.y, 0.f);
                *(float4*)(yrow + 4 * p) = o;
            }
        }
    }
    __syncthreads();

    // ---- Phase C: h2 = y @ W2 + b2. thread = (col-pair cpc, node-group gc) ----
    const int cpc = tid & 63, gc = tid >> 6;       // cols {2cpc,2cpc+1}, nodes 16gc..+15
    {
        ull acc[2][8];
        const float2 bb = *(const float2*)(b2 + layer * 128 + 2 * cpc);
        #pragma unroll
        for (int q = 0; q < 8; q++) { acc[0][q] = pack2(bb.x, bb.x);
                                      acc[1][q] = pack2(bb.y, bb.y); }
        for (int s = 0; s < 4; s++) {
            float* buf = Wsl + (s & 1) * 8192;
            if (s < 3) cp_slab(Wsl + ((s + 1) & 1) * 8192, W2g + (s + 1) * 8192, tid);
            if (s < 3) asm volatile("cp.async.wait_group 1;");
            else       asm volatile("cp.async.wait_group 0;");
            __syncthreads();
            #pragma unroll 4
            for (int kk = 0; kk < 64; kk++) {
                const int k = s * 64 + kk;
                const float* yrow = yT + k * NP + 16 * gc;
                const float2 wv = *(const float2*)(buf + kk * 128 + 2 * cpc);
                const ull w0 = pack2(wv.x, wv.x), w1 = pack2(wv.y, wv.y);
                #pragma unroll
                for (int c = 0; c < 4; c++) {
                    const ulonglong2 yv = *(const ulonglong2*)(yrow + 4 * c);
                    fma2(acc[0][2 * c + 0], yv.x, w0);
                    fma2(acc[0][2 * c + 1], yv.y, w0);
                    fma2(acc[1][2 * c + 0], yv.x, w1);
                    fma2(acc[1][2 * c + 1], yv.y, w1);
                }
            }
            __syncthreads();                       // also protects h2s alias of h0T
        }
        #pragma unroll
        for (int c = 0; c < 2; c++)
            #pragma unroll
            for (int p = 0; p < 8; p++) {
                const float2 u = unpack2(acc[c][p]);
                const int n = 16 * gc + 2 * p;
                h2s[(n + 0) * 132 + 2 * cpc + c] = u.x;
                h2s[(n + 1) * 132 + 2 * cpc + c] = u.y;
            }
    }
    __syncthreads();

    // ---- Phase D: LayerNorm + residual + ReLU ----
    {
        const int warp = tid >> 5, lane = tid & 31;
        const float4 w4  = ((const float4*)(lnw + layer * 128))[lane];
        const float4 bb4 = ((const float4*)(lnb + layer * 128))[lane];
        #pragma unroll
        for (int i = 0; i < 8; i++) {
            const int n = warp * 8 + i;
            const int gn = n0 + n;
            const float4 h = *(const float4*)(h2s + n * 132 + lane * 4);
            float s  = h.x + h.y + h.z + h.w;
            float s2 = h.x * h.x + h.y * h.y + h.z * h.z + h.w * h.w;
            #pragma unroll
            for (int off = 16; off; off >>= 1) {
                s  += __shfl_xor_sync(0xffffffffu, s,  off);
                s2 += __shfl_xor_sync(0xffffffffu, s2, off);
            }
            const float mu  = s  * (1.f / 128.f);
            const float var = s2 * (1.f / 128.f) - mu * mu;
            const float rs  = rsqrtf(var + 1e-5f);
            if (gn < N_NODES) {
                const size_t gi = (size_t)gn * 32 + lane;
                const float4 xr = ((const float4*)x)[gi];
                float4 o;
                o.x = fmaxf((h.x - mu) * rs * w4.x + bb4.x + xr.x, 0.f);
                o.y = fmaxf((h.y - mu) * rs * w4.y + bb4.y + xr.y, 0.f);
                o.z = fmaxf((h.z - mu) * rs * w4.z + bb4.z + xr.z, 0.f);
                o.w = fmaxf((h.w - mu) * rs * w4.w + bb4.w + xr.w, 0.f);
                ((float4*)x)[gi] = o;
            }
        }
    }
}

// ---------------- output projection: out = x @ Wout + bout ------------------------
#define OUT_SMEM ((8704 + 8192) * 4)
__global__ void __launch_bounds__(256) out_kernel(
    const float* __restrict__ x, const float* __restrict__ Wo,
    const float* __restrict__ bo, float* __restrict__ out)
{
    extern __shared__ float sm[];
    float* xT = sm;                    // 128 x 68 (swizzled transpose)
    float* Ws = sm + 8704;             // 128 x 64
    const int tid = threadIdx.x;
    const int n0  = blockIdx.x * 64;

    #pragma unroll
    for (int i = 0; i < 8; i++)
        ((float4*)Ws)[tid + i * 256] = ((const float4*)Wo)[tid + i * 256];

    {
        const float4* x4 = (const float4*)x;
        #pragma unroll
        for (int it = 0; it < 8; it++) {
            const int idx  = tid + it * 256;
            const int node = idx >> 5, kq = idx & 31;
            const int gn   = n0 + node;
            float4 xv = make_float4(0.f, 0.f, 0.f, 0.f);
            if (gn < N_NODES) xv = x4[(size_t)gn * 32 + kq];
            const int nn = node ^ ((kq & 7) << 2);
            xT[(4 * kq + 0) * NP + nn] = xv.x;
            xT[(4 * kq + 1) * NP + nn] = xv.y;
            xT[(4 * kq + 2) * NP + nn] = xv.z;
            xT[(4 * kq + 3) * NP + nn] = xv.w;
        }
    }
    __syncthreads();

    const int cp = tid & 31, g = tid >> 5;         // cols {2cp,2cp+1}, nodes 8g..+7
    ull acc[2][4];
    const float2 bb = *(const float2*)(bo + 2 * cp);
    #pragma unroll
    for (int q = 0; q < 4; q++) { acc[0][q] = pack2(bb.x, bb.x);
                                  acc[1][q] = pack2(bb.y, bb.y); }
    #pragma unroll 4
    for (int k = 0; k < 128; k++) {
        const int sw = ((k >> 2) & 7) << 2;
        const float* row = xT + k * NP;
        const float2 wv = *(const float2*)(Ws + k * 64 + 2 * cp);
        const ull w0 = pack2(wv.x, wv.x), w1 = pack2(wv.y, wv.y);
        #pragma unroll
        for (int c = 0; c < 2; c++) {
            const ulonglong2 xv = *(const ulonglong2*)(row + ((8 * g + 4 * c) ^ sw));
            fma2(acc[0][2 * c + 0], xv.x, w0);
            fma2(acc[0][2 * c + 1], xv.y, w0);
            fma2(acc[1][2 * c + 0], xv.x, w1);
            fma2(acc[1][2 * c + 1], xv.y, w1);
        }
    }
    #pragma unroll
    for (int p = 0; p < 4; p++) {
        const float2 u0 = unpack2(acc[0][p]);      // col 2cp,  nodes {2p,2p+1}
        const float2 u1 = unpack2(acc[1][p]);      // col 2cp+1
        const int n = 8 * g + 2 * p;
        if (n0 + n < N_NODES)
            *(float2*)(out + (size_t)(n0 + n) * C_OUT + 2 * cp)
                = make_float2(u0.x, u1.x);
        if (n0 + n + 1 < N_NODES)
            *(float2*)(out + (size_t)(n0 + n + 1) * C_OUT + 2 * cp)
                = make_float2(u0.y, u1.y);
    }
}

// ---------------- launch ------------------------------------------------------------
extern "C" void kernel_launch(void* const* d_in, const int* in_sizes, int n_in,
                              void* d_out, int out_size) {
    (void)in_sizes; (void)n_in; (void)out_size;
    const float* x   = (const float*)d_in[0];
    const void*  ei  = d_in[1];
    const float* ea  = (const float*)d_in[2];
    const float* We  = (const float*)d_in[3];
    const float* be  = (const float*)d_in[4];
    const float* W1  = (const float*)d_in[5];
    const float* b1  = (const float*)d_in[6];
    const float* W2  = (const float*)d_in[7];
    const float* b2  = (const float*)d_in[8];
    const float* lnw = (const float*)d_in[9];
    const float* lnb = (const float*)d_in[10];
    const float* Wo  = (const float*)d_in[11];
    const float* bo  = (const float*)d_in[12];
    float* out = (float*)d_out;

    void *pgx = nullptr, *pagg = nullptr;
    cudaGetSymbolAddress(&pgx, g_x);
    cudaGetSymbolAddress(&pagg, g_agg);
    float* gx   = (float*)pgx;
    float* gagg = (float*)pagg;

    cudaFuncSetAttribute(node_kernel, cudaFuncAttributeMaxDynamicSharedMemorySize,
                         NODE_SMEM);
    cudaFuncSetAttribute(out_kernel, cudaFuncAttributeMaxDynamicSharedMemorySize,
                         OUT_SMEM);

    const int n_tiles = (N_NODES + 63) / 64;       // 1563

    probe_kernel<<<1, 32>>>((const int*)ei);
    cudaMemcpyAsync(gx, x, (size_t)N_NODES * C_HID * sizeof(float),
                    cudaMemcpyDeviceToDevice);

    for (int l = 0; l < N_LAYERS; l++) {
        cudaMemsetAsync(gagg, 0, (size_t)N_NODES * C_HID * sizeof(float));
        edge_kernel<<<1184, 256>>>(ea, ei, gx, We, be, gagg, l);
        node_kernel<<<n_tiles, 256, NODE_SMEM>>>(gx, gagg, W1, b1, W2, b2,
                                                 lnw, lnb, l);
    }
    out_kernel<<<n_tiles, 256, OUT_SMEM>>>(gx, Wo, bo, out);
}

// round 7
// speedup vs baseline: 1.2127x; 1.2127x over previous
#include <cuda_runtime.h>
#include <cstdint>

#define N_NODES 100000
#define N_EDGES 1600000
#define C_HID   128
#define E_DIM   32
#define C_OUT   64
#define N_LAYERS 4

typedef unsigned long long ull;

// ---------------- scratch (static device globals; no allocation) ----------------
__device__ float g_x  [(size_t)N_NODES * C_HID];
__device__ float g_agg[(size_t)N_NODES * C_HID];
__device__ int   g_idx64_flag;

// ---------------- packed fp32 helpers --------------------------------------------
__device__ __forceinline__ ull pack2(float x, float y) {
    ull r; asm("mov.b64 %0, {%1, %2};" : "=l"(r) : "f"(x), "f"(y)); return r;
}
__device__ __forceinline__ float2 unpack2(ull v) {
    float2 r; asm("mov.b64 {%0, %1}, %2;" : "=f"(r.x), "=f"(r.y) : "l"(v)); return r;
}
__device__ __forceinline__ void fma2(ull& acc, ull a, ull b) {
    asm("fma.rn.f32x2 %0, %1, %2, %0;" : "+l"(acc) : "l"(a), "l"(b));
}
__device__ __forceinline__ void red4(float* p, float4 v) {
    asm volatile("red.global.add.v4.f32 [%0], {%1, %2, %3, %4};"
                 :: "l"(p), "f"(v.x), "f"(v.y), "f"(v.z), "f"(v.w) : "memory");
}
__device__ __forceinline__ void cp16(unsigned int s, const void* g) {
    asm volatile("cp.async.ca.shared.global [%0], [%1], 16;" :: "r"(s), "l"(g));
}
__device__ __forceinline__ void cp_commit() {
    asm volatile("cp.async.commit_group;");
}

// copy one 8192-float (32KB) weight slab: 256 threads x 8 x 16B
__device__ __forceinline__ void cp_slab(float* dst, const float* src, int tid) {
    unsigned int s = (unsigned int)__cvta_generic_to_shared(dst) + tid * 16;
    const char* g = (const char*)src + tid * 16;
    #pragma unroll
    for (int i = 0; i < 8; i++) cp16(s + i * 4096, g + i * 4096);
    cp_commit();
}

// ---------------- dtype probe: edge_index int64 vs int32 -------------------------
__global__ void probe_kernel(const int* __restrict__ ei) {
    if (threadIdx.x == 0 && blockIdx.x == 0) {
        int all0 = 1;
        for (int i = 1; i < 64; i += 2) all0 &= (ei[i] == 0);
        g_idx64_flag = all0;
    }
}

// ---------------- edge kernel v4: 16 edges/iter, 128-thr blocks ------------------
// smem weights; per iter: 32 LDS.128 amortized over 16 edges (8 wf/edge vs 16 in
// v2). 16 src + 16 dst indices fill all 32 lanes. 1.6M/16 = 100k exact iters.
__global__ void __launch_bounds__(128, 4) edge_kernel(
    const float* __restrict__ ea, const void* __restrict__ ei_raw,
    const float* __restrict__ x, const float* __restrict__ We,
    const float* __restrict__ be, float* __restrict__ agg, int layer)
{
    __shared__ float4 Ws[E_DIM * 32];   // [k][lane] = We[k][4l..4l+3], 16KB
    __shared__ float  bes[C_HID];

    const float4* We4 = (const float4*)(We + (size_t)layer * E_DIM * C_HID);
    #pragma unroll
    for (int i = 0; i < 8; i++) Ws[threadIdx.x + i * 128] = We4[threadIdx.x + i * 128];
    bes[threadIdx.x] = be[layer * C_HID + threadIdx.x];
    __syncthreads();

    const int use64 = g_idx64_flag;
    const long long* ei64 = (const long long*)ei_raw;
    const int*       ei32 = (const int*)ei_raw;
    const float4*    x4   = (const float4*)x;
    const ulonglong2* Ws2 = (const ulonglong2*)Ws;

    const int lane   = threadIdx.x & 31;
    const int warp   = (blockIdx.x * blockDim.x + threadIdx.x) >> 5;
    const int nwarps = (gridDim.x * blockDim.x) >> 5;

    const ull be01 = pack2(bes[lane * 4 + 0], bes[lane * 4 + 1]);
    const ull be23 = pack2(bes[lane * 4 + 2], bes[lane * 4 + 3]);

    for (int p = warp; p < N_EDGES / 16; p += nwarps) {
        const int e0 = p * 16;

        // edge attrs: a[j] = ea[e0+j][lane], 16 coalesced 128B loads
        float a[16];
        #pragma unroll
        for (int j = 0; j < 16; j++) a[j] = ea[(e0 + j) * E_DIM + lane];

        // indices: lanes 0..15 -> src[e0+lane], lanes 16..31 -> dst[e0+lane-16]
        int sv;
        if (use64) sv = (int)((lane < 16) ? ei64[e0 + lane]
                                          : ei64[N_EDGES + e0 + lane - 16]);
        else       sv = (lane < 16) ? ei32[e0 + lane]
                                    : ei32[N_EDGES + e0 + lane - 16];

        ull accA[16], accB[16];
        #pragma unroll
        for (int j = 0; j < 16; j++) { accA[j] = be01; accB[j] = be23; }

        #pragma unroll 8
        for (int k = 0; k < E_DIM; k++) {
            const ulonglong2 w = Ws2[k * 32 + lane];
            #pragma unroll
            for (int j = 0; j < 16; j++) {
                const float ak = __shfl_sync(0xffffffffu, a[j], k);
                const ull av = pack2(ak, ak);
                fma2(accA[j], av, w.x);
                fma2(accB[j], av, w.y);
            }
        }

        #pragma unroll
        for (int j = 0; j < 16; j++) {
            const int s = __shfl_sync(0xffffffffu, sv, j);
            const int d = __shfl_sync(0xffffffffu, sv, 16 + j);
            const float4 xv = x4[(size_t)s * 32 + lane];
            const float2 pA = unpack2(accA[j]);
            const float2 pB = unpack2(accB[j]);
            float4 m;
            m.x = fmaxf(pA.x + xv.x, 0.f);
            m.y = fmaxf(pA.y + xv.y, 0.f);
            m.z = fmaxf(pB.x + xv.z, 0.f);
            m.w = fmaxf(pB.y + xv.w, 0.f);
            red4(agg + (size_t)d * C_HID + lane * 4, m);
        }
    }
}

// ---------------- node kernel v2: 64-node tiles, 2 cols/thread, cp.async db ------
#define NP 68
#define SM_H0T 0                        // 128*68 = 8704 floats (h2s aliases: 64*132)
#define SM_YT  8704                     // 256*68 = 17408 floats
#define SM_WSL (8704 + 17408)           // 2 x 8192 floats (double buffer)
#define NODE_SMEM ((8704 + 17408 + 16384) * 4)

__global__ void __launch_bounds__(256) node_kernel(
    float* __restrict__ x, const float* __restrict__ agg,
    const float* __restrict__ W1, const float* __restrict__ b1,
    const float* __restrict__ W2, const float* __restrict__ b2,
    const float* __restrict__ lnw, const float* __restrict__ lnb, int layer)
{
    extern __shared__ float sm[];
    float* h0T = sm + SM_H0T;
    float* h2s = sm + SM_H0T;          // alias (h0T dead after Phase B)
    float* yT  = sm + SM_YT;
    float* Wsl = sm + SM_WSL;

    const int tid = threadIdx.x;
    const int n0  = blockIdx.x * 64;

    const float* W1g = W1 + (size_t)layer * 128 * 256;
    const float* W2g = W2 + (size_t)layer * 256 * 128;

    cp_slab(Wsl, W1g, tid);            // prefetch W1 slab 0 under Phase A

    // ---- Phase A: h0T[k][n'] = x[n][k] + agg[n][k], n' = n ^ ((k>>2 & 7)<<2) ----
    {
        const float4* x4 = (const float4*)x;
        const float4* a4 = (const float4*)agg;
        #pragma unroll
        for (int it = 0; it < 8; it++) {
            const int idx  = tid + it * 256;      // 0..2047
            const int node = idx >> 5, kq = idx & 31;
            const int gn   = n0 + node;
            float4 xv = make_float4(0.f, 0.f, 0.f, 0.f), av = xv;
            if (gn < N_NODES) {
                xv = x4[(size_t)gn * 32 + kq];
                av = a4[(size_t)gn * 32 + kq];
            }
            const int nn = node ^ ((kq & 7) << 2);
            h0T[(4 * kq + 0) * NP + nn] = xv.x + av.x;
            h0T[(4 * kq + 1) * NP + nn] = xv.y + av.y;
            h0T[(4 * kq + 2) * NP + nn] = xv.z + av.z;
            h0T[(4 * kq + 3) * NP + nn] = xv.w + av.w;
        }
    }
    __syncthreads();

    // ---- Phase B: y = relu(h0 @ W1 + b1). thread = (col-pair cp, node-group g) ----
    const int cp = tid & 127, g = tid >> 7;        // cols {2cp,2cp+1}, nodes 32g..+31
    {
        ull acc[2][16];
        const float2 bb = *(const float2*)(b1 + layer * 256 + 2 * cp);
        #pragma unroll
        for (int q = 0; q < 16; q++) { acc[0][q] = pack2(bb.x, bb.x);
                                       acc[1][q] = pack2(bb.y, bb.y); }
        for (int s = 0; s < 4; s++) {
            float* buf = Wsl + (s & 1) * 8192;
            if (s < 3) cp_slab(Wsl + ((s + 1) & 1) * 8192, W1g + (s + 1) * 8192, tid);
            if (s < 3) asm volatile("cp.async.wait_group 1;");
            else       asm volatile("cp.async.wait_group 0;");
            __syncthreads();
            #pragma unroll 4
            for (int kk = 0; kk < 32; kk++) {
                const int k  = s * 32 + kk;
                const int sw = ((k >> 2) & 7) << 2;
                const float* hrow = h0T + k * NP + 32 * g;
                const float2 wv = *(const float2*)(buf + kk * 256 + 2 * cp);
                const ull w0 = pack2(wv.x, wv.x), w1 = pack2(wv.y, wv.y);
                #pragma unroll
                for (int c = 0; c < 8; c++) {
                    const ulonglong2 hv = *(const ulonglong2*)(hrow + ((4 * c) ^ sw));
                    fma2(acc[0][2 * c + 0], hv.x, w0);
                    fma2(acc[0][2 * c + 1], hv.y, w0);
                    fma2(acc[1][2 * c + 0], hv.x, w1);
                    fma2(acc[1][2 * c + 1], hv.y, w1);
                }
            }
            __syncthreads();
        }
        cp_slab(Wsl, W2g, tid);                    // prefetch W2 slab 0
        #pragma unroll
        for (int c = 0; c < 2; c++) {
            float* yrow = yT + (2 * cp + c) * NP + 32 * g;
            #pragma unroll
            for (int p = 0; p < 8; p++) {
                const float2 u = unpack2(acc[c][2 * p + 0]);
                const float2 v = unpack2(acc[c][2 * p + 1]);
                float4 o;
                o.x = fmaxf(u.x, 0.f); o.y = fmaxf(u.y, 0.f);
                o.z = fmaxf(v.x, 0.f); o.w = fmaxf(v.y, 0.f);
                *(float4*)(yrow + 4 * p) = o;
            }
        }
    }
    __syncthreads();

    // ---- Phase C: h2 = y @ W2 + b2. thread = (col-pair cpc, node-group gc) ----
    const int cpc = tid & 63, gc = tid >> 6;       // cols {2cpc,2cpc+1}, nodes 16gc..+15
    {
        ull acc[2][8];
        const float2 bb = *(const float2*)(b2 + layer * 128 + 2 * cpc);
        #pragma unroll
        for (int q = 0; q < 8; q++) { acc[0][q] = pack2(bb.x, bb.x);
                                      acc[1][q] = pack2(bb.y, bb.y); }
        for (int s = 0; s < 4; s++) {
            float* buf = Wsl + (s & 1) * 8192;
            if (s < 3) cp_slab(Wsl + ((s + 1) & 1) * 8192, W2g + (s + 1) * 8192, tid);
            if (s < 3) asm volatile("cp.async.wait_group 1;");
            else       asm volatile("cp.async.wait_group 0;");
            __syncthreads();
            #pragma unroll 4
            for (int kk = 0; kk < 64; kk++) {
                const int k = s * 64 + kk;
                const float* yrow = yT + k * NP + 16 * gc;
                const float2 wv = *(const float2*)(buf + kk * 128 + 2 * cpc);
                const ull w0 = pack2(wv.x, wv.x), w1 = pack2(wv.y, wv.y);
                #pragma unroll
                for (int c = 0; c < 4; c++) {
                    const ulonglong2 yv = *(const ulonglong2*)(yrow + 4 * c);
                    fma2(acc[0][2 * c + 0], yv.x, w0);
                    fma2(acc[0][2 * c + 1], yv.y, w0);
                    fma2(acc[1][2 * c + 0], yv.x, w1);
                    fma2(acc[1][2 * c + 1], yv.y, w1);
                }
            }
            __syncthreads();                       // also protects h2s alias of h0T
        }
        #pragma unroll
        for (int c = 0; c < 2; c++)
            #pragma unroll
            for (int p = 0; p < 8; p++) {
                const float2 u = unpack2(acc[c][p]);
                const int n = 16 * gc + 2 * p;
                h2s[(n + 0) * 132 + 2 * cpc + c] = u.x;
                h2s[(n + 1) * 132 + 2 * cpc + c] = u.y;
            }
    }
    __syncthreads();

    // ---- Phase D: LayerNorm + residual + ReLU ----
    {
        const int warp = tid >> 5, lane = tid & 31;
        const float4 w4  = ((const float4*)(lnw + layer * 128))[lane];
        const float4 bb4 = ((const float4*)(lnb + layer * 128))[lane];
        #pragma unroll
        for (int i = 0; i < 8; i++) {
            const int n = warp * 8 + i;
            const int gn = n0 + n;
            const float4 h = *(const float4*)(h2s + n * 132 + lane * 4);
            float s  = h.x + h.y + h.z + h.w;
            float s2 = h.x * h.x + h.y * h.y + h.z * h.z + h.w * h.w;
            #pragma unroll
            for (int off = 16; off; off >>= 1) {
                s  += __shfl_xor_sync(0xffffffffu, s,  off);
                s2 += __shfl_xor_sync(0xffffffffu, s2, off);
            }
            const float mu  = s  * (1.f / 128.f);
            const float var = s2 * (1.f / 128.f) - mu * mu;
            const float rs  = rsqrtf(var + 1e-5f);
            if (gn < N_NODES) {
                const size_t gi = (size_t)gn * 32 + lane;
                const float4 xr = ((const float4*)x)[gi];
                float4 o;
                o.x = fmaxf((h.x - mu) * rs * w4.x + bb4.x + xr.x, 0.f);
                o.y = fmaxf((h.y - mu) * rs * w4.y + bb4.y + xr.y, 0.f);
                o.z = fmaxf((h.z - mu) * rs * w4.z + bb4.z + xr.z, 0.f);
                o.w = fmaxf((h.w - mu) * rs * w4.w + bb4.w + xr.w, 0.f);
                ((float4*)x)[gi] = o;
            }
        }
    }
}

// ---------------- output projection: out = x @ Wout + bout ------------------------
#define OUT_SMEM ((8704 + 8192) * 4)
__global__ void __launch_bounds__(256) out_kernel(
    const float* __restrict__ x, const float* __restrict__ Wo,
    const float* __restrict__ bo, float* __restrict__ out)
{
    extern __shared__ float sm[];
    float* xT = sm;                    // 128 x 68 (swizzled transpose)
    float* Ws = sm + 8704;             // 128 x 64
    const int tid = threadIdx.x;
    const int n0  = blockIdx.x * 64;

    #pragma unroll
    for (int i = 0; i < 8; i++)
        ((float4*)Ws)[tid + i * 256] = ((const float4*)Wo)[tid + i * 256];

    {
        const float4* x4 = (const float4*)x;
        #pragma unroll
        for (int it = 0; it < 8; it++) {
            const int idx  = tid + it * 256;
            const int node = idx >> 5, kq = idx & 31;
            const int gn   = n0 + node;
            float4 xv = make_float4(0.f, 0.f, 0.f, 0.f);
            if (gn < N_NODES) xv = x4[(size_t)gn * 32 + kq];
            const int nn = node ^ ((kq & 7) << 2);
            xT[(4 * kq + 0) * NP + nn] = xv.x;
            xT[(4 * kq + 1) * NP + nn] = xv.y;
            xT[(4 * kq + 2) * NP + nn] = xv.z;
            xT[(4 * kq + 3) * NP + nn] = xv.w;
        }
    }
    __syncthreads();

    const int cp = tid & 31, g = tid >> 5;         // cols {2cp,2cp+1}, nodes 8g..+7
    ull acc[2][4];
    const float2 bb = *(const float2*)(bo + 2 * cp);
    #pragma unroll
    for (int q = 0; q < 4; q++) { acc[0][q] = pack2(bb.x, bb.x);
                                  acc[1][q] = pack2(bb.y, bb.y); }
    #pragma unroll 4
    for (int k = 0; k < 128; k++) {
        const int sw = ((k >> 2) & 7) << 2;
        const float* row = xT + k * NP;
        const float2 wv = *(const float2*)(Ws + k * 64 + 2 * cp);
        const ull w0 = pack2(wv.x, wv.x), w1 = pack2(wv.y, wv.y);
        #pragma unroll
        for (int c = 0; c < 2; c++) {
            const ulonglong2 xv = *(const ulonglong2*)(row + ((8 * g + 4 * c) ^ sw));
            fma2(acc[0][2 * c + 0], xv.x, w0);
            fma2(acc[0][2 * c + 1], xv.y, w0);
            fma2(acc[1][2 * c + 0], xv.x, w1);
            fma2(acc[1][2 * c + 1], xv.y, w1);
        }
    }
    #pragma unroll
    for (int p = 0; p < 4; p++) {
        const float2 u0 = unpack2(acc[0][p]);      // col 2cp,  nodes {2p,2p+1}
        const float2 u1 = unpack2(acc[1][p]);      // col 2cp+1
        const int n = 8 * g + 2 * p;
        if (n0 + n < N_NODES)
            *(float2*)(out + (size_t)(n0 + n) * C_OUT + 2 * cp)
                = make_float2(u0.x, u1.x);
        if (n0 + n + 1 < N_NODES)
            *(float2*)(out + (size_t)(n0 + n + 1) * C_OUT + 2 * cp)
                = make_float2(u0.y, u1.y);
    }
}

// ---------------- launch ------------------------------------------------------------
extern "C" void kernel_launch(void* const* d_in, const int* in_sizes, int n_in,
                              void* d_out, int out_size) {
    (void)in_sizes; (void)n_in; (void)out_size;
    const float* x   = (const float*)d_in[0];
    const void*  ei  = d_in[1];
    const float* ea  = (const float*)d_in[2];
    const float* We  = (const float*)d_in[3];
    const float* be  = (const float*)d_in[4];
    const float* W1  = (const float*)d_in[5];
    const float* b1  = (const float*)d_in[6];
    const float* W2  = (const float*)d_in[7];
    const float* b2  = (const float*)d_in[8];
    const float* lnw = (const float*)d_in[9];
    const float* lnb = (const float*)d_in[10];
    const float* Wo  = (const float*)d_in[11];
    const float* bo  = (const float*)d_in[12];
    float* out = (float*)d_out;

    void *pgx = nullptr, *pagg = nullptr;
    cudaGetSymbolAddress(&pgx, g_x);
    cudaGetSymbolAddress(&pagg, g_agg);
    float* gx   = (float*)pgx;
    float* gagg = (float*)pagg;

    cudaFuncSetAttribute(node_kernel, cudaFuncAttributeMaxDynamicSharedMemorySize,
                         NODE_SMEM);
    cudaFuncSetAttribute(out_kernel, cudaFuncAttributeMaxDynamicSharedMemorySize,
                         OUT_SMEM);

    const int n_tiles = (N_NODES + 63) / 64;       // 1563

    probe_kernel<<<1, 32>>>((const int*)ei);
    cudaMemcpyAsync(gx, x, (size_t)N_NODES * C_HID * sizeof(float),
                    cudaMemcpyDeviceToDevice);

    for (int l = 0; l < N_LAYERS; l++) {
        cudaMemsetAsync(gagg, 0, (size_t)N_NODES * C_HID * sizeof(float));
        edge_kernel<<<592, 128>>>(ea, ei, gx, We, be, gagg, l);
        node_kernel<<<n_tiles, 256, NODE_SMEM>>>(gx, gagg, W1, b1, W2, b2,
                                                 lnw, lnb, l);
    }
    out_kernel<<<n_tiles, 256, OUT_SMEM>>>(gx, Wo, bo, out);
}

// round 8
// speedup vs baseline: 1.2132x; 1.0004x over previous
#include <cuda_runtime.h>
#include <cstdint>

#define N_NODES 100000
#define N_EDGES 1600000
#define C_HID   128
#define E_DIM   32
#define C_OUT   64
#define N_LAYERS 4

typedef unsigned long long ull;

// ---------------- scratch (static device globals; no allocation) ----------------
__device__ float g_x  [(size_t)N_NODES * C_HID];
__device__ float g_agg[(size_t)N_NODES * C_HID];
__device__ int   g_idx64_flag;

// ---------------- packed fp32 helpers --------------------------------------------
__device__ __forceinline__ ull pack2(float x, float y) {
    ull r; asm("mov.b64 %0, {%1, %2};" : "=l"(r) : "f"(x), "f"(y)); return r;
}
__device__ __forceinline__ float2 unpack2(ull v) {
    float2 r; asm("mov.b64 {%0, %1}, %2;" : "=f"(r.x), "=f"(r.y) : "l"(v)); return r;
}
__device__ __forceinline__ void fma2(ull& acc, ull a, ull b) {
    asm("fma.rn.f32x2 %0, %1, %2, %0;" : "+l"(acc) : "l"(a), "l"(b));
}
__device__ __forceinline__ void red4(float* p, float4 v) {
    asm volatile("red.global.add.v4.f32 [%0], {%1, %2, %3, %4};"
                 :: "l"(p), "f"(v.x), "f"(v.y), "f"(v.z), "f"(v.w) : "memory");
}
__device__ __forceinline__ void cp16(unsigned int s, const void* g) {
    asm volatile("cp.async.ca.shared.global [%0], [%1], 16;" :: "r"(s), "l"(g));
}
__device__ __forceinline__ void cp_commit() {
    asm volatile("cp.async.commit_group;");
}

// copy one 8192-float (32KB) weight slab: 256 threads x 8 x 16B
__device__ __forceinline__ void cp_slab(float* dst, const float* src, int tid) {
    unsigned int s = (unsigned int)__cvta_generic_to_shared(dst) + tid * 16;
    const char* g = (const char*)src + tid * 16;
    #pragma unroll
    for (int i = 0; i < 8; i++) cp16(s + i * 4096, g + i * 4096);
    cp_commit();
}

// ---------------- dtype probe: edge_index int64 vs int32 -------------------------
__global__ void probe_kernel(const int* __restrict__ ei) {
    if (threadIdx.x == 0 && blockIdx.x == 0) {
        int all0 = 1;
        for (int i = 1; i < 64; i += 2) all0 &= (ei[i] == 0);
        g_idx64_flag = all0;
    }
}

// ---------------- edge kernel v4: 16 edges/iter, 128-thr blocks ------------------
// smem weights; per iter: 32 LDS.128 amortized over 16 edges (8 wf/edge vs 16 in
// v2). 16 src + 16 dst indices fill all 32 lanes. 1.6M/16 = 100k exact iters.
__global__ void __launch_bounds__(128, 4) edge_kernel(
    const float* __restrict__ ea, const void* __restrict__ ei_raw,
    const float* __restrict__ x, const float* __restrict__ We,
    const float* __restrict__ be, float* __restrict__ agg, int layer)
{
    __shared__ float4 Ws[E_DIM * 32];   // [k][lane] = We[k][4l..4l+3], 16KB
    __shared__ float  bes[C_HID];

    const float4* We4 = (const float4*)(We + (size_t)layer * E_DIM * C_HID);
    #pragma unroll
    for (int i = 0; i < 8; i++) Ws[threadIdx.x + i * 128] = We4[threadIdx.x + i * 128];
    bes[threadIdx.x] = be[layer * C_HID + threadIdx.x];
    __syncthreads();

    const int use64 = g_idx64_flag;
    const long long* ei64 = (const long long*)ei_raw;
    const int*       ei32 = (const int*)ei_raw;
    const float4*    x4   = (const float4*)x;
    const ulonglong2* Ws2 = (const ulonglong2*)Ws;

    const int lane   = threadIdx.x & 31;
    const int warp   = (blockIdx.x * blockDim.x + threadIdx.x) >> 5;
    const int nwarps = (gridDim.x * blockDim.x) >> 5;

    const ull be01 = pack2(bes[lane * 4 + 0], bes[lane * 4 + 1]);
    const ull be23 = pack2(bes[lane * 4 + 2], bes[lane * 4 + 3]);

    for (int p = warp; p < N_EDGES / 16; p += nwarps) {
        const int e0 = p * 16;

        // edge attrs: a[j] = ea[e0+j][lane], 16 coalesced 128B loads
        float a[16];
        #pragma unroll
        for (int j = 0; j < 16; j++) a[j] = ea[(e0 + j) * E_DIM + lane];

        // indices: lanes 0..15 -> src[e0+lane], lanes 16..31 -> dst[e0+lane-16]
        int sv;
        if (use64) sv = (int)((lane < 16) ? ei64[e0 + lane]
                                          : ei64[N_EDGES + e0 + lane - 16]);
        else       sv = (lane < 16) ? ei32[e0 + lane]
                                    : ei32[N_EDGES + e0 + lane - 16];

        ull accA[16], accB[16];
        #pragma unroll
        for (int j = 0; j < 16; j++) { accA[j] = be01; accB[j] = be23; }

        #pragma unroll 8
        for (int k = 0; k < E_DIM; k++) {
            const ulonglong2 w = Ws2[k * 32 + lane];
            #pragma unroll
            for (int j = 0; j < 16; j++) {
                const float ak = __shfl_sync(0xffffffffu, a[j], k);
                const ull av = pack2(ak, ak);
                fma2(accA[j], av, w.x);
                fma2(accB[j], av, w.y);
            }
        }

        #pragma unroll
        for (int j = 0; j < 16; j++) {
            const int s = __shfl_sync(0xffffffffu, sv, j);
            const int d = __shfl_sync(0xffffffffu, sv, 16 + j);
            const float4 xv = x4[(size_t)s * 32 + lane];
            const float2 pA = unpack2(accA[j]);
            const float2 pB = unpack2(accB[j]);
            float4 m;
            m.x = fmaxf(pA.x + xv.x, 0.f);
            m.y = fmaxf(pA.y + xv.y, 0.f);
            m.z = fmaxf(pB.x + xv.z, 0.f);
            m.w = fmaxf(pB.y + xv.w, 0.f);
            red4(agg + (size_t)d * C_HID + lane * 4, m);
        }
    }
}

// ---------------- node kernel v2: 64-node tiles, 2 cols/thread, cp.async db ------
#define NP 68
#define SM_H0T 0                        // 128*68 = 8704 floats (h2s aliases: 64*132)
#define SM_YT  8704                     // 256*68 = 17408 floats
#define SM_WSL (8704 + 17408)           // 2 x 8192 floats (double buffer)
#define NODE_SMEM ((8704 + 17408 + 16384) * 4)

__global__ void __launch_bounds__(256) node_kernel(
    float* __restrict__ x, const float* __restrict__ agg,
    const float* __restrict__ W1, const float* __restrict__ b1,
    const float* __restrict__ W2, const float* __restrict__ b2,
    const float* __restrict__ lnw, const float* __restrict__ lnb, int layer)
{
    extern __shared__ float sm[];
    float* h0T = sm + SM_H0T;
    float* h2s = sm + SM_H0T;          // alias (h0T dead after Phase B)
    float* yT  = sm + SM_YT;
    float* Wsl = sm + SM_WSL;

    const int tid = threadIdx.x;
    const int n0  = blockIdx.x * 64;

    const float* W1g = W1 + (size_t)layer * 128 * 256;
    const float* W2g = W2 + (size_t)layer * 256 * 128;

    cp_slab(Wsl, W1g, tid);            // prefetch W1 slab 0 under Phase A

    // ---- Phase A: h0T[k][n'] = x[n][k] + agg[n][k], n' = n ^ ((k>>2 & 7)<<2) ----
    {
        const float4* x4 = (const float4*)x;
        const float4* a4 = (const float4*)agg;
        #pragma unroll
        for (int it = 0; it < 8; it++) {
            const int idx  = tid + it * 256;      // 0..2047
            const int node = idx >> 5, kq = idx & 31;
            const int gn   = n0 + node;
            float4 xv = make_float4(0.f, 0.f, 0.f, 0.f), av = xv;
            if (gn < N_NODES) {
                xv = x4[(size_t)gn * 32 + kq];
                av = a4[(size_t)gn * 32 + kq];
            }
            const int nn = node ^ ((kq & 7) << 2);
            h0T[(4 * kq + 0) * NP + nn] = xv.x + av.x;
            h0T[(4 * kq + 1) * NP + nn] = xv.y + av.y;
            h0T[(4 * kq + 2) * NP + nn] = xv.z + av.z;
            h0T[(4 * kq + 3) * NP + nn] = xv.w + av.w;
        }
    }
    __syncthreads();

    // ---- Phase B: y = relu(h0 @ W1 + b1). thread = (col-pair cp, node-group g) ----
    const int cp = tid & 127, g = tid >> 7;        // cols {2cp,2cp+1}, nodes 32g..+31
    {
        ull acc[2][16];
        const float2 bb = *(const float2*)(b1 + layer * 256 + 2 * cp);
        #pragma unroll
        for (int q = 0; q < 16; q++) { acc[0][q] = pack2(bb.x, bb.x);
                                       acc[1][q] = pack2(bb.y, bb.y); }
        for (int s = 0; s < 4; s++) {
            float* buf = Wsl + (s & 1) * 8192;
            if (s < 3) cp_slab(Wsl + ((s + 1) & 1) * 8192, W1g + (s + 1) * 8192, tid);
            if (s < 3) asm volatile("cp.async.wait_group 1;");
            else       asm volatile("cp.async.wait_group 0;");
            __syncthreads();
            #pragma unroll 4
            for (int kk = 0; kk < 32; kk++) {
                const int k  = s * 32 + kk;
                const int sw = ((k >> 2) & 7) << 2;
                const float* hrow = h0T + k * NP + 32 * g;
                const float2 wv = *(const float2*)(buf + kk * 256 + 2 * cp);
                const ull w0 = pack2(wv.x, wv.x), w1 = pack2(wv.y, wv.y);
                #pragma unroll
                for (int c = 0; c < 8; c++) {
                    const ulonglong2 hv = *(const ulonglong2*)(hrow + ((4 * c) ^ sw));
                    fma2(acc[0][2 * c + 0], hv.x, w0);
                    fma2(acc[0][2 * c + 1], hv.y, w0);
                    fma2(acc[1][2 * c + 0], hv.x, w1);
                    fma2(acc[1][2 * c + 1], hv.y, w1);
                }
            }
            __syncthreads();
        }
        cp_slab(Wsl, W2g, tid);                    // prefetch W2 slab 0
        #pragma unroll
        for (int c = 0; c < 2; c++) {
            float* yrow = yT + (2 * cp + c) * NP + 32 * g;
            #pragma unroll
            for (int p = 0; p < 8; p++) {
                const float2 u = unpack2(acc[c][2 * p + 0]);
                const float2 v = unpack2(acc[c][2 * p + 1]);
                float4 o;
                o.x = fmaxf(u.x, 0.f); o.y = fmaxf(u.y, 0.f);
                o.z = fmaxf(v.x, 0.f); o.w = fmaxf(v.y, 0.f);
                *(float4*)(yrow + 4 * p) = o;
            }
        }
    }
    __syncthreads();

    // ---- Phase C: h2 = y @ W2 + b2. thread = (col-pair cpc, node-group gc) ----
    const int cpc = tid & 63, gc = tid >> 6;       // cols {2cpc,2cpc+1}, nodes 16gc..+15
    {
        ull acc[2][8];
        const float2 bb = *(const float2*)(b2 + layer * 128 + 2 * cpc);
        #pragma unroll
        for (int q = 0; q < 8; q++) { acc[0][q] = pack2(bb.x, bb.x);
                                      acc[1][q] = pack2(bb.y, bb.y); }
        for (int s = 0; s < 4; s++) {
            float* buf = Wsl + (s & 1) * 8192;
            if (s < 3) cp_slab(Wsl + ((s + 1) & 1) * 8192, W2g + (s + 1) * 8192, tid);
            if (s < 3) asm volatile("cp.async.wait_group 1;");
            else       asm volatile("cp.async.wait_group 0;");
            __syncthreads();
            #pragma unroll 4
            for (int kk = 0; kk < 64; kk++) {
                const int k = s * 64 + kk;
                const float* yrow = yT + k * NP + 16 * gc;
                const float2 wv = *(const float2*)(buf + kk * 128 + 2 * cpc);
                const ull w0 = pack2(wv.x, wv.x), w1 = pack2(wv.y, wv.y);
                #pragma unroll
                for (int c = 0; c < 4; c++) {
                    const ulonglong2 yv = *(const ulonglong2*)(yrow + 4 * c);
                    fma2(acc[0][2 * c + 0], yv.x, w0);
                    fma2(acc[0][2 * c + 1], yv.y, w0);
                    fma2(acc[1][2 * c + 0], yv.x, w1);
                    fma2(acc[1][2 * c + 1], yv.y, w1);
                }
            }
            __syncthreads();                       // also protects h2s alias of h0T
        }
        #pragma unroll
        for (int c = 0; c < 2; c++)
            #pragma unroll
            for (int p = 0; p < 8; p++) {
                const float2 u = unpack2(acc[c][p]);
                const int n = 16 * gc + 2 * p;
                h2s[(n + 0) * 132 + 2 * cpc + c] = u.x;
                h2s[(n + 1) * 132 + 2 * cpc + c] = u.y;
            }
    }
    __syncthreads();

    // ---- Phase D: LayerNorm + residual + ReLU ----
    {
        const int warp = tid >> 5, lane = tid & 31;
        const float4 w4  = ((const float4*)(lnw + layer * 128))[lane];
        const float4 bb4 = ((const float4*)(lnb + layer * 128))[lane];
        #pragma unroll
        for (int i = 0; i < 8; i++) {
            const int n = warp * 8 + i;
            const int gn = n0 + n;
            const float4 h = *(const float4*)(h2s + n * 132 + lane * 4);
            float s  = h.x + h.y + h.z + h.w;
            float s2 = h.x * h.x + h.y * h.y + h.z * h.z + h.w * h.w;
            #pragma unroll
            for (int off = 16; off; off >>= 1) {
                s  += __shfl_xor_sync(0xffffffffu, s,  off);
                s2 += __shfl_xor_sync(0xffffffffu, s2, off);
            }
            const float mu  = s  * (1.f / 128.f);
            const float var = s2 * (1.f / 128.f) - mu * mu;
            const float rs  = rsqrtf(var + 1e-5f);
            if (gn < N_NODES) {
                const size_t gi = (size_t)gn * 32 + lane;
                const float4 xr = ((const float4*)x)[gi];
                float4 o;
                o.x = fmaxf((h.x - mu) * rs * w4.x + bb4.x + xr.x, 0.f);
                o.y = fmaxf((h.y - mu) * rs * w4.y + bb4.y + xr.y, 0.f);
                o.z = fmaxf((h.z - mu) * rs * w4.z + bb4.z + xr.z, 0.f);
                o.w = fmaxf((h.w - mu) * rs * w4.w + bb4.w + xr.w, 0.f);
                ((float4*)x)[gi] = o;
            }
        }
    }
}

// ---------------- output projection: out = x @ Wout + bout ------------------------
#define OUT_SMEM ((8704 + 8192) * 4)
__global__ void __launch_bounds__(256) out_kernel(
    const float* __restrict__ x, const float* __restrict__ Wo,
    const float* __restrict__ bo, float* __restrict__ out)
{
    extern __shared__ float sm[];
    float* xT = sm;                    // 128 x 68 (swizzled transpose)
    float* Ws = sm + 8704;             // 128 x 64
    const int tid = threadIdx.x;
    const int n0  = blockIdx.x * 64;

    #pragma unroll
    for (int i = 0; i < 8; i++)
        ((float4*)Ws)[tid + i * 256] = ((const float4*)Wo)[tid + i * 256];

    {
        const float4* x4 = (const float4*)x;
        #pragma unroll
        for (int it = 0; it < 8; it++) {
            const int idx  = tid + it * 256;
            const int node = idx >> 5, kq = idx & 31;
            const int gn   = n0 + node;
            float4 xv = make_float4(0.f, 0.f, 0.f, 0.f);
            if (gn < N_NODES) xv = x4[(size_t)gn * 32 + kq];
            const int nn = node ^ ((kq & 7) << 2);
            xT[(4 * kq + 0) * NP + nn] = xv.x;
            xT[(4 * kq + 1) * NP + nn] = xv.y;
            xT[(4 * kq + 2) * NP + nn] = xv.z;
            xT[(4 * kq + 3) * NP + nn] = xv.w;
        }
    }
    __syncthreads();

    const int cp = tid & 31, g = tid >> 5;         // cols {2cp,2cp+1}, nodes 8g..+7
    ull acc[2][4];
    const float2 bb = *(const float2*)(bo + 2 * cp);
    #pragma unroll
    for (int q = 0; q < 4; q++) { acc[0][q] = pack2(bb.x, bb.x);
                                  acc[1][q] = pack2(bb.y, bb.y); }
    #pragma unroll 4
    for (int k = 0; k < 128; k++) {
        const int sw = ((k >> 2) & 7) << 2;
        const float* row = xT + k * NP;
        const float2 wv = *(const float2*)(Ws + k * 64 + 2 * cp);
        const ull w0 = pack2(wv.x, wv.x), w1 = pack2(wv.y, wv.y);
        #pragma unroll
        for (int c = 0; c < 2; c++) {
            const ulonglong2 xv = *(const ulonglong2*)(row + ((8 * g + 4 * c) ^ sw));
            fma2(acc[0][2 * c + 0], xv.x, w0);
            fma2(acc[0][2 * c + 1], xv.y, w0);
            fma2(acc[1][2 * c + 0], xv.x, w1);
            fma2(acc[1][2 * c + 1], xv.y, w1);
        }
    }
    #pragma unroll
    for (int p = 0; p < 4; p++) {
        const float2 u0 = unpack2(acc[0][p]);      // col 2cp,  nodes {2p,2p+1}
        const float2 u1 = unpack2(acc[1][p]);      // col 2cp+1
        const int n = 8 * g + 2 * p;
        if (n0 + n < N_NODES)
            *(float2*)(out + (size_t)(n0 + n) * C_OUT + 2 * cp)
                = make_float2(u0.x, u1.x);
        if (n0 + n + 1 < N_NODES)
            *(float2*)(out + (size_t)(n0 + n + 1) * C_OUT + 2 * cp)
                = make_float2(u0.y, u1.y);
    }
}

// ---------------- launch ------------------------------------------------------------
extern "C" void kernel_launch(void* const* d_in, const int* in_sizes, int n_in,
                              void* d_out, int out_size) {
    (void)in_sizes; (void)n_in; (void)out_size;
    const float* x   = (const float*)d_in[0];
    const void*  ei  = d_in[1];
    const float* ea  = (const float*)d_in[2];
    const float* We  = (const float*)d_in[3];
    const float* be  = (const float*)d_in[4];
    const float* W1  = (const float*)d_in[5];
    const float* b1  = (const float*)d_in[6];
    const float* W2  = (const float*)d_in[7];
    const float* b2  = (const float*)d_in[8];
    const float* lnw = (const float*)d_in[9];
    const float* lnb = (const float*)d_in[10];
    const float* Wo  = (const float*)d_in[11];
    const float* bo  = (const float*)d_in[12];
    float* out = (float*)d_out;

    void *pgx = nullptr, *pagg = nullptr;
    cudaGetSymbolAddress(&pgx, g_x);
    cudaGetSymbolAddress(&pagg, g_agg);
    float* gx   = (float*)pgx;
    float* gagg = (float*)pagg;

    cudaFuncSetAttribute(node_kernel, cudaFuncAttributeMaxDynamicSharedMemorySize,
                         NODE_SMEM);
    cudaFuncSetAttribute(out_kernel, cudaFuncAttributeMaxDynamicSharedMemorySize,
                         OUT_SMEM);

    const int n_tiles = (N_NODES + 63) / 64;       // 1563

    probe_kernel<<<1, 32>>>((const int*)ei);
    cudaMemcpyAsync(gx, x, (size_t)N_NODES * C_HID * sizeof(float),
                    cudaMemcpyDeviceToDevice);

    for (int l = 0; l < N_LAYERS; l++) {
        cudaMemsetAsync(gagg, 0, (size_t)N_NODES * C_HID * sizeof(float));
        edge_kernel<<<592, 128>>>(ea, ei, gx, We, be, gagg, l);
        node_kernel<<<n_tiles, 256, NODE_SMEM>>>(gx, gagg, W1, b1, W2, b2,
                                                 lnw, lnb, l);
    }
    out_kernel<<<n_tiles, 256, OUT_SMEM>>>(gx, Wo, bo, out);
}